// round 4
// baseline (speedup 1.0000x reference)
#include <cuda_runtime.h>
#include <cstdint>

#define N_FINE   200000
#define N_COARSE 50000
#define ROW_F4   128   // (2 groups * 128 ch * 2 cplx) floats / 4 = 128 float4 per row

// ---------- device scratch (no runtime allocation allowed) ----------
__device__ int g_unpool_map[N_FINE];   // zero-init matches jnp.zeros; scatter is idempotent

struct __align__(16) EdgeRec { int src; int dst; float c; float s; };
__device__ EdgeRec g_edge[N_FINE];     // 3.2 MB: fully resolved per-edge record

// ---------- phase 1: inverse permutation ----------
__global__ void build_map_kernel(const int* __restrict__ nodes) {
    int i = blockIdx.x * blockDim.x + threadIdx.x;
    if (i < N_COARSE) g_unpool_map[nodes[i]] = i;
}

// ---------- phase 2: resolve edges -> {coarse src row, fine dst row, cos, sin} ----------
__global__ void build_edge_kernel(const int*    __restrict__ edge_src,
                                  const int*    __restrict__ edge_dst,
                                  const float2* __restrict__ conn) {
    int e = blockIdx.x * blockDim.x + threadIdx.x;
    if (e < N_FINE) {
        EdgeRec r;
        r.src = g_unpool_map[edge_src[e]];
        r.dst = edge_dst[e];
        float2 cs = conn[e];
        r.c = cs.x;
        r.s = cs.y;
        g_edge[e] = r;
    }
}

// ---------- phase 3: gather row, rotate group 1, scatter ----------
// One warp per edge. Thread j handles float4s j, j+32 (group 0: copy) and
// j+64, j+96 (group 1: multiply by conj(c,s)). MLP=4, warp-uniform metadata.
//
// Stores use WRITE-THROUGH (__stwt): the 410 MB output stream is touch-once,
// and keeping it out of L2 entirely leaves the full 126 MB L2 for the 102 MB
// x working set, whose rows are each gathered ~4x. This targets the ~90 MB of
// x read amplification seen at the DRAM level with __stcs.
__global__ void __launch_bounds__(256)
unpool_kernel(const float4* __restrict__ x, float4* __restrict__ out) {
    int t = blockIdx.x * blockDim.x + threadIdx.x;
    int e = t >> 5;        // edge index — uniform across the warp
    int j = t & 31;        // float4 lane
    if (e >= N_FINE) return;

    // Single warp-uniform 16-byte load for all per-edge metadata.
    int4 raw = *reinterpret_cast<const int4*>(&g_edge[e]);
    int   src = raw.x;
    int   dst = raw.y;
    float c   = __int_as_float(raw.z);
    float s   = __int_as_float(raw.w);

    const float4* xr = x + (size_t)src * ROW_F4;
    float4 v0 = xr[j];          // group 0
    float4 v1 = xr[j + 32];     // group 0
    float4 v2 = xr[j + 64];     // group 1
    float4 v3 = xr[j + 96];     // group 1

    // (re + i*im) * (c - i*s)
    float4 r2, r3;
    r2.x = fmaf(v2.x, c,  v2.y * s);
    r2.y = fmaf(v2.y, c, -v2.x * s);
    r2.z = fmaf(v2.z, c,  v2.w * s);
    r2.w = fmaf(v2.w, c, -v2.z * s);
    r3.x = fmaf(v3.x, c,  v3.y * s);
    r3.y = fmaf(v3.y, c, -v3.x * s);
    r3.z = fmaf(v3.z, c,  v3.w * s);
    r3.w = fmaf(v3.w, c, -v3.z * s);

    float4* o = out + (size_t)dst * ROW_F4;
    __stwt(o + j,      v0);
    __stwt(o + j + 32, v1);
    __stwt(o + j + 64, r2);
    __stwt(o + j + 96, r3);
}

extern "C" void kernel_launch(void* const* d_in, const int* in_sizes, int n_in,
                              void* d_out, int out_size) {
    // metadata order: x, unpool_connection, unpool_nodes, unpool_edges, num_nodes
    const float4* x     = (const float4*)d_in[0];
    const float2* conn  = (const float2*)d_in[1];
    const int*    nodes = (const int*)d_in[2];
    const int*    edges = (const int*)d_in[3];   // [2, N_FINE]: row0=src, row1=dst
    float4*       out   = (float4*)d_out;

    (void)in_sizes; (void)n_in; (void)out_size;

    build_map_kernel<<<(N_COARSE + 255) / 256, 256>>>(nodes);
    build_edge_kernel<<<(N_FINE + 255) / 256, 256>>>(edges, edges + N_FINE, conn);

    const long long total = (long long)N_FINE * 32;   // 6.4M threads
    unpool_kernel<<<(unsigned)((total + 255) / 256), 256>>>(x, out);
}

// round 7
// speedup vs baseline: 1.0127x; 1.0127x over previous
#include <cuda_runtime.h>
#include <cstdint>

#define N_FINE   200000
#define N_COARSE 50000
#define ROW_F4   128   // (2 groups * 128 ch * 2 cplx) floats / 4 = 128 float4 per row

// ---------- device scratch (no runtime allocation allowed) ----------
__device__ int g_unpool_map[N_FINE];   // zero-init matches jnp.zeros; scatter is idempotent

struct __align__(16) EdgeRec { int src; int dst; float c; float s; };
__device__ EdgeRec g_edge[N_FINE];     // 3.2 MB: fully resolved per-edge record

struct F8 { float4 a, b; };            // one 32-byte chunk

// 256-bit non-coherent load with L2 evict_last (ptxas on sm_103a requires the
// policy modifier on v8.b32/v4.b64 widths). Biases the 102 MB x working set
// (each row gathered ~4x) to stay resident in the 126 MB L2.
__device__ __forceinline__ F8 ldg_el_256(const F8* p) {
    F8 v;
    asm volatile(
        "ld.global.nc.L2::evict_last.v8.f32 {%0,%1,%2,%3,%4,%5,%6,%7}, [%8];"
        : "=f"(v.a.x), "=f"(v.a.y), "=f"(v.a.z), "=f"(v.a.w),
          "=f"(v.b.x), "=f"(v.b.y), "=f"(v.b.z), "=f"(v.b.w)
        : "l"(p));
    return v;
}

// ---------- phase 1: inverse permutation ----------
__global__ void build_map_kernel(const int* __restrict__ nodes) {
    int i = blockIdx.x * blockDim.x + threadIdx.x;
    if (i < N_COARSE) g_unpool_map[nodes[i]] = i;
}

// ---------- phase 2: resolve edges -> {coarse src row, fine dst row, cos, sin} ----------
__global__ void build_edge_kernel(const int*    __restrict__ edge_src,
                                  const int*    __restrict__ edge_dst,
                                  const float2* __restrict__ conn) {
    int e = blockIdx.x * blockDim.x + threadIdx.x;
    if (e < N_FINE) {
        EdgeRec r;
        r.src = g_unpool_map[edge_src[e]];
        r.dst = edge_dst[e];
        float2 cs = conn[e];
        r.c = cs.x;
        r.s = cs.y;
        g_edge[e] = r;
    }
}

// ---------- phase 3: gather row, rotate group 1, scatter ----------
// One warp per edge; row = 64 chunks of 32 B. Thread j handles chunk j
// (group 0: plain copy) and chunk j+32 (group 1: complex multiply by
// conj(c,s)). Loads: 256-bit + L2 evict_last (pin x in L2). Stores: __stcs
// evict-first so the touch-once 410 MB output doesn't displace x.
__global__ void __launch_bounds__(256)
unpool_kernel(const float4* __restrict__ x, float4* __restrict__ out) {
    int t = blockIdx.x * blockDim.x + threadIdx.x;
    int e = t >> 5;        // edge index — uniform across the warp
    int j = t & 31;        // 32-byte chunk lane
    if (e >= N_FINE) return;

    // Single warp-uniform 16-byte load for all per-edge metadata.
    int4 raw = *reinterpret_cast<const int4*>(&g_edge[e]);
    int   src = raw.x;
    int   dst = raw.y;
    float c   = __int_as_float(raw.z);
    float s   = __int_as_float(raw.w);

    const F8* xr = reinterpret_cast<const F8*>(x + (size_t)src * ROW_F4);
    F8 v0 = ldg_el_256(xr + j);        // group 0 (chunks 0..31)
    F8 v1 = ldg_el_256(xr + j + 32);   // group 1 (chunks 32..63)

    // (re + i*im) * (c - i*s) on the 4 complex pairs in v1
    F8 r1;
    r1.a.x = fmaf(v1.a.x, c,  v1.a.y * s);
    r1.a.y = fmaf(v1.a.y, c, -v1.a.x * s);
    r1.a.z = fmaf(v1.a.z, c,  v1.a.w * s);
    r1.a.w = fmaf(v1.a.w, c, -v1.a.z * s);
    r1.b.x = fmaf(v1.b.x, c,  v1.b.y * s);
    r1.b.y = fmaf(v1.b.y, c, -v1.b.x * s);
    r1.b.z = fmaf(v1.b.z, c,  v1.b.w * s);
    r1.b.w = fmaf(v1.b.w, c, -v1.b.z * s);

    float4* o = out + (size_t)dst * ROW_F4;
    __stcs(o + 2 * j,          v0.a);
    __stcs(o + 2 * j + 1,      v0.b);
    __stcs(o + 2 * j + 64,     r1.a);
    __stcs(o + 2 * j + 65,     r1.b);
}

extern "C" void kernel_launch(void* const* d_in, const int* in_sizes, int n_in,
                              void* d_out, int out_size) {
    // metadata order: x, unpool_connection, unpool_nodes, unpool_edges, num_nodes
    const float4* x     = (const float4*)d_in[0];
    const float2* conn  = (const float2*)d_in[1];
    const int*    nodes = (const int*)d_in[2];
    const int*    edges = (const int*)d_in[3];   // [2, N_FINE]: row0=src, row1=dst
    float4*       out   = (float4*)d_out;

    (void)in_sizes; (void)n_in; (void)out_size;

    build_map_kernel<<<(N_COARSE + 255) / 256, 256>>>(nodes);
    build_edge_kernel<<<(N_FINE + 255) / 256, 256>>>(edges, edges + N_FINE, conn);

    const long long total = (long long)N_FINE * 32;   // 6.4M threads
    unpool_kernel<<<(unsigned)((total + 255) / 256), 256>>>(x, out);
}